// round 2
// baseline (speedup 1.0000x reference)
#include <cuda_runtime.h>
#include <cuda_bf16.h>
#include <cstdint>

// ---------------------------------------------------------------------------
// Shapes (fixed by the bench)
// ---------------------------------------------------------------------------
#define BATCH 16
#define TLEN  2048
#define CDIM  200
#define DDIM  2048
#define KTOT  (BATCH * TLEN)   // 32768
#define CPAD  256              // classes padded to 16x m16 tiles

// GEMM tiling (family-portable mma.sync path; no tcgen05 on base sm_103)
#define KC       64                     // k per smem chunk
#define NTILE    128                    // d columns per CTA
#define KSPLIT   8
#define KPERCTA  (KTOT / KSPLIT)        // 4096
#define NCHUNKS  (KPERCTA / KC)         // 64

// smem: A 2 x 32KB (256 rows x 128B), B 2 x 16KB (128 rows x 128B)
#define SM_A0 0
#define SM_A1 32768
#define SM_B0 65536
#define SM_B1 (65536 + 16384)
#define SMEM_BYTES (65536 + 32768)      // 98304

// ---------------------------------------------------------------------------
// Scratch (device globals: allocation-free per harness rules)
// ---------------------------------------------------------------------------
__device__ __align__(128) __nv_bfloat16 g_Amat[(size_t)CPAD * KTOT]; // 16 MB
__device__ float g_sums[CPAD * DDIM];                                // 2 MB
__device__ int   g_counts[CPAD];

// ---------------------------------------------------------------------------
// helpers
// ---------------------------------------------------------------------------
__device__ __forceinline__ uint32_t smem_u32(const void* p) {
    uint32_t a;
    asm("{ .reg .u64 t; cvta.to.shared.u64 t, %1; cvt.u32.u64 %0, t; }"
        : "=r"(a) : "l"(p));
    return a;
}
__device__ __forceinline__ uint32_t sw128(uint32_t off) {
    return off ^ ((off >> 3) & 0x70);
}
__device__ __forceinline__ void sts128(uint32_t a, uint32_t x, uint32_t y,
                                       uint32_t z, uint32_t w) {
    asm volatile("st.shared.v4.b32 [%0], {%1,%2,%3,%4};"
                 :: "r"(a), "r"(x), "r"(y), "r"(z), "r"(w) : "memory");
}
__device__ __forceinline__ uint32_t pack_bf16x2(float lo, float hi) {
    uint32_t r;
    asm("cvt.rn.satfinite.bf16x2.f32 %0, %1, %2;" : "=r"(r) : "f"(hi), "f"(lo));
    return r;
}
__device__ __forceinline__ void cp_async16(uint32_t saddr, const void* gaddr) {
    asm volatile("cp.async.cg.shared.global [%0], [%1], 16;"
                 :: "r"(saddr), "l"(gaddr) : "memory");
}
__device__ __forceinline__ void cp_commit() {
    asm volatile("cp.async.commit_group;" ::: "memory");
}
__device__ __forceinline__ void cp_wait0() {
    asm volatile("cp.async.wait_group 0;" ::: "memory");
}
__device__ __forceinline__ void ldmatrix_x4(uint32_t* r, uint32_t addr) {
    asm volatile("ldmatrix.sync.aligned.m8n8.x4.shared.b16 {%0,%1,%2,%3}, [%4];"
                 : "=r"(r[0]), "=r"(r[1]), "=r"(r[2]), "=r"(r[3]) : "r"(addr));
}
__device__ __forceinline__ void mma16816(float* c, const uint32_t* a,
                                         uint32_t b0, uint32_t b1) {
    asm volatile(
        "mma.sync.aligned.m16n8k16.row.col.f32.bf16.bf16.f32 "
        "{%0,%1,%2,%3}, {%4,%5,%6,%7}, {%8,%9}, {%0,%1,%2,%3};"
        : "+f"(c[0]), "+f"(c[1]), "+f"(c[2]), "+f"(c[3])
        : "r"(a[0]), "r"(a[1]), "r"(a[2]), "r"(a[3]), "r"(b0), "r"(b1));
}

// ---------------------------------------------------------------------------
// Stage 0: zero scratch (graph replays reuse globals)
// ---------------------------------------------------------------------------
__global__ void zero_kernel() {
    int i = blockIdx.x * 256 + threadIdx.x;
    if (i < CPAD * DDIM) g_sums[i] = 0.0f;
    if (i < CPAD) g_counts[i] = 0;
}

// ---------------------------------------------------------------------------
// Stage 1: bf16 mask matrix Amat[256][32768] (K-major) + per-class counts.
// Block = 64 consecutive bt for all 256 classes; smem transpose keeps both
// the act reads and the Amat writes coalesced.
// ---------------------------------------------------------------------------
__global__ __launch_bounds__(256) void build_mask_kernel(
    const int* __restrict__ act, const int* __restrict__ vid) {
    __shared__ __nv_bfloat16 m[CPAD][66];
    __shared__ int vids[CPAD];

    int tid = threadIdx.x;
    int bt0 = blockIdx.x * 64;
    int b = bt0 >> 11;  // T = 2048

    for (int c = tid; c < CPAD; c += 256)
        vids[c] = (c < CDIM) ? vid[b * CDIM + c] : 0;
    __syncthreads();

    const __nv_bfloat16 one = __float2bfloat16(1.0f);
    const __nv_bfloat16 zero = __float2bfloat16(0.0f);

    for (int idx = tid; idx < 64 * CDIM; idx += 256) {
        int r = idx / CDIM, c = idx - r * CDIM;
        int a = act[(size_t)(bt0 + r) * CDIM + c];
        m[c][r] = (a != 0 && vids[c] != 0) ? one : zero;
    }
    for (int idx = tid; idx < (CPAD - CDIM) * 64; idx += 256)
        m[CDIM + (idx >> 6)][idx & 63] = zero;
    __syncthreads();

    int lid = tid & 31, wid = tid >> 5;
    for (int c = wid; c < CPAD; c += 8) {
        uint32_t v = *(const uint32_t*)&m[c][2 * lid];
        *(uint32_t*)((char*)g_Amat + (size_t)c * (KTOT * 2) + (bt0 + 2 * lid) * 2) = v;
        int cnt = (int)((v & 0xFFFFu) != 0) + (int)((v >> 16) != 0);
        cnt = __reduce_add_sync(0xFFFFFFFFu, cnt);
        if (lid == 0 && c < CDIM && cnt) atomicAdd(&g_counts[c], cnt);
    }
}

// ---------------------------------------------------------------------------
// Stage 2: mma.sync bf16 GEMM  sums[c,d] += sum_k mask[c,k] * feats[k,d]
// CTA: M=256 x N=128, 16 warps (4x4), warp tile 64x32, double-buffered KC=64.
// ---------------------------------------------------------------------------
__global__ __launch_bounds__(512, 1) void gemm_kernel(const float* __restrict__ feats) {
    extern __shared__ char smem[];
    const uint32_t sb = smem_u32(smem);
    const int tid = threadIdx.x;
    const int lane = tid & 31, wid = tid >> 5;
    const int wm = wid & 3;        // m block: wm*64
    const int wn = wid >> 2;       // n block: wn*32
    const int d0 = blockIdx.x * NTILE;
    const int kbase = blockIdx.y * KPERCTA;

    // B-load addressing: thread -> (d column, k quarter)
    const int dcol = tid & 127;
    const int kq = tid >> 7;       // 0..3, covers k = kq*16 .. +15

    float acc[4][4][4];
#pragma unroll
    for (int i = 0; i < 4; i++)
#pragma unroll
        for (int j = 0; j < 4; j++)
#pragma unroll
            for (int r = 0; r < 4; r++) acc[i][j][r] = 0.0f;

    // ldmatrix per-lane row offsets (pre-swizzle), per m-tile / n-pair
    uint32_t a_off[4];
#pragma unroll
    for (int mt = 0; mt < 4; mt++) {
        int rowA = wm * 64 + mt * 16 + (lane & 15);
        a_off[mt] = (uint32_t)(rowA * 128 + (lane >> 4) * 16);
    }
    uint32_t b_off[2];
#pragma unroll
    for (int np = 0; np < 2; np++) {
        int rowB = wn * 32 + np * 16 + ((lane >> 4) << 3) + (lane & 7);
        b_off[np] = (uint32_t)(rowB * 128 + ((lane >> 3) & 1) * 16);
    }

    float fst[16];

    // ---- load chunk ck into stage s: A via cp.async, B into registers ----
    auto issue_loads = [&](int ck, int s) {
        const int k0 = kbase + ck * KC;
        const uint32_t abase = sb + (s ? SM_A1 : SM_A0);
#pragma unroll
        for (int it = 0; it < 4; it++) {
            int idx = it * 512 + tid;
            int c = idx >> 3, seg = idx & 7;
            const void* g = g_Amat + (size_t)c * KTOT + k0 + seg * 8;
            cp_async16(abase + sw128((uint32_t)(c * 128 + seg * 16)), g);
        }
        cp_commit();
        const float* fp = feats + (size_t)(k0 + kq * 16) * DDIM + d0 + dcol;
#pragma unroll
        for (int j = 0; j < 16; j++) fst[j] = fp[(size_t)j * DDIM];
    };
    // ---- convert + store B tile to stage s ----
    auto store_b = [&](int s) {
        const uint32_t bbase = sb + (s ? SM_B1 : SM_B0);
        uint32_t p[8];
#pragma unroll
        for (int j = 0; j < 8; j++) p[j] = pack_bf16x2(fst[2 * j], fst[2 * j + 1]);
        uint32_t o0 = (uint32_t)(dcol * 128 + kq * 32);
        sts128(bbase + sw128(o0), p[0], p[1], p[2], p[3]);
        sts128(bbase + sw128(o0 + 16), p[4], p[5], p[6], p[7]);
    };
    // ---- compute on stage s ----
    auto compute = [&](int s) {
        const uint32_t abase = sb + (s ? SM_A1 : SM_A0);
        const uint32_t bbase = sb + (s ? SM_B1 : SM_B0);
#pragma unroll
        for (int ks = 0; ks < 4; ks++) {
            uint32_t a[4][4], b[2][4];
#pragma unroll
            for (int mt = 0; mt < 4; mt++)
                ldmatrix_x4(a[mt], abase + sw128(a_off[mt] + ks * 32));
#pragma unroll
            for (int np = 0; np < 2; np++)
                ldmatrix_x4(b[np], bbase + sw128(b_off[np] + ks * 32));
#pragma unroll
            for (int mt = 0; mt < 4; mt++)
#pragma unroll
                for (int nt = 0; nt < 4; nt++)
                    mma16816(acc[mt][nt], a[mt],
                             b[nt >> 1][(nt & 1) * 2], b[nt >> 1][(nt & 1) * 2 + 1]);
        }
    };

    // prologue
    issue_loads(0, 0);
    cp_wait0();
    store_b(0);
    __syncthreads();

#pragma unroll 1
    for (int ck = 0; ck < NCHUNKS; ck++) {
        const int s = ck & 1;
        if (ck + 1 < NCHUNKS) issue_loads(ck + 1, s ^ 1);
        compute(s);
        if (ck + 1 < NCHUNKS) {
            store_b(s ^ 1);
            cp_wait0();
            __syncthreads();
        }
    }

    // epilogue: atomic accumulate into global partial sums
    const int row = lane >> 2;
    const int col = (lane & 3) * 2;
#pragma unroll
    for (int mt = 0; mt < 4; mt++) {
#pragma unroll
        for (int nt = 0; nt < 4; nt++) {
            int cls = wm * 64 + mt * 16 + row;
            int dd = d0 + wn * 32 + nt * 8 + col;
            float* gp = g_sums + (size_t)cls * DDIM + dd;
            atomicAdd(gp, acc[mt][nt][0]);
            atomicAdd(gp + 1, acc[mt][nt][1]);
            float* gp2 = gp + 8 * DDIM;
            atomicAdd(gp2, acc[mt][nt][2]);
            atomicAdd(gp2 + 1, acc[mt][nt][3]);
        }
    }
}

// ---------------------------------------------------------------------------
// Stage 3: momentum update
// ---------------------------------------------------------------------------
__global__ void finalize_kernel(const float* __restrict__ proto,
                                float* __restrict__ out) {
    int i = blockIdx.x * 256 + threadIdx.x;
    if (i >= CDIM * DDIM) return;
    int c = i >> 11;  // DDIM = 2048
    float p = proto[i];
    int cnt = g_counts[c];
    float mean = g_sums[i] / fmaxf((float)cnt, 1.0f);
    out[i] = (cnt > 0) ? (0.999f * p + 0.001f * mean) : p;
}

// ---------------------------------------------------------------------------
// Launch
// ---------------------------------------------------------------------------
extern "C" void kernel_launch(void* const* d_in, const int* in_sizes, int n_in,
                              void* d_out, int out_size) {
    const float* feats = (const float*)d_in[0];
    const int* act = (const int*)d_in[1];
    const int* vid = (const int*)d_in[2];
    const float* proto = (const float*)d_in[3];
    float* out = (float*)d_out;

    cudaFuncSetAttribute(gemm_kernel, cudaFuncAttributeMaxDynamicSharedMemorySize,
                         SMEM_BYTES);

    zero_kernel<<<(CPAD * DDIM + 255) / 256, 256>>>();
    build_mask_kernel<<<KTOT / 64, 256>>>(act, vid);
    gemm_kernel<<<dim3(DDIM / NTILE, KSPLIT), 512, SMEM_BYTES>>>(feats);
    finalize_kernel<<<(CDIM * DDIM + 255) / 256, 256>>>(proto, out);
}